// round 9
// baseline (speedup 1.0000x reference)
#include <cuda_runtime.h>
#include <cstdint>

namespace {
constexpr int kB = 16, kH = 256, kC = 128, kW = 128;
constexpr long kCC = (long)kC * kC;
}

// Scratch (device globals: allocation-free contract).
__device__ float g_q[(size_t)kB * kW * kH * kC];   // q (B,W,H,C); reused as m5 (B,W,C,H)
__device__ float g_k[(size_t)kB * kW * kH * kC];   // k (B,W,H,C); reused as m6 (B,H,C,W)
__device__ float g_v[(size_t)kB * kW * kH * kC];   // v (B,W,H,C)
__device__ float g_s[(size_t)kB * kW * kC * kC];   // exp(scores) (B,W,D,C)
__device__ float g_wn[(size_t)kB * kW * kC * kC];  // wn (B,W,E,C)
__device__ float g_inv[(size_t)kB * kC * kC];      // 1/sum_w exp (B,D,C)

__device__ __forceinline__ uint32_t smem_u32(const void* p) {
  uint32_t a;
  asm("{ .reg .u64 t; cvta.to.shared.u64 t, %1; cvt.u32.u64 %0, t; }" : "=r"(a) : "l"(p));
  return a;
}
__device__ __forceinline__ uint32_t f2tf32(float f) {
  uint32_t r;
  asm("cvt.rna.tf32.f32 %0, %1;" : "=r"(r) : "f"(f));
  return r;
}

// exp on the FMA pipe (no MUFU): exp(x) = 2^r * e^f, deg-5 Taylor on |f|<=ln2/2.
__device__ __forceinline__ float fast_exp(float x) {
  x = fminf(fmaxf(x, -30.f), 30.f);
  float r = rintf(x * 1.44269504f);
  float f = fmaf(r, -0.6931471805599453f, x);
  float p = 1.f + f * (1.f + f * (0.5f + f * (0.16666667f +
                f * (0.041666667f + f * 0.0083333333f))));
  return p * __int_as_float(((int)r + 127) << 23);
}

// SMEM row stride (words). 36 => ldmatrix phases span all 32 banks (4r+c).
constexpr int kLds = 36;
constexpr int kBufW = 128 * kLds;  // words per stage

// Load 16 k-words of one row into registers. KC=true: k unit stride (float4).
template <bool KC>
__device__ __forceinline__ void ldg16(float4 r[4], const float* __restrict__ p, long sK) {
  if (KC) {
#pragma unroll
    for (int i = 0; i < 4; i++) r[i] = reinterpret_cast<const float4*>(p)[i];
  } else {
#pragma unroll
    for (int i = 0; i < 4; i++) {
      r[i].x = p[(long)(i * 4 + 0) * sK];
      r[i].y = p[(long)(i * 4 + 1) * sK];
      r[i].z = p[(long)(i * 4 + 2) * sK];
      r[i].w = p[(long)(i * 4 + 3) * sK];
    }
  }
}

// Convert to tf32 (optionally *nrm first) and store 16 contiguous words to smem.
template <bool NORM>
__device__ __forceinline__ void sts16(uint32_t* __restrict__ dst, const float4 a[4],
                                      const float4 n[4]) {
#pragma unroll
  for (int i = 0; i < 4; i++) {
    float4 v = a[i];
    if (NORM) {
      v.x *= n[i].x; v.y *= n[i].y; v.z *= n[i].z; v.w *= n[i].w;
    }
    uint32_t t0 = f2tf32(v.x), t1 = f2tf32(v.y), t2 = f2tf32(v.z), t3 = f2tf32(v.w);
    asm volatile("st.shared.v4.b32 [%0], {%1,%2,%3,%4};"
                 :: "l"(dst + i * 4), "r"(t0), "r"(t1), "r"(t2), "r"(t3));
  }
}

// Direct gmem -> smem (short-lived register temps only).
template <bool KC, bool NORM>
__device__ __forceinline__ void load_store16(uint32_t* __restrict__ dst,
                                             const float* __restrict__ src, long sK,
                                             const float* __restrict__ nsrc) {
  float4 a[4], n[4];
  ldg16<KC>(a, src, sK);
  if (NORM) ldg16<KC>(n, nsrc, sK);
  sts16<NORM>(dst, a, n);
}

__device__ __forceinline__ void ldsm_x4(uint32_t r[4], uint32_t addr) {
  asm volatile("ldmatrix.sync.aligned.m8n8.x4.shared.b16 {%0,%1,%2,%3}, [%4];"
               : "=r"(r[0]), "=r"(r[1]), "=r"(r[2]), "=r"(r[3]) : "r"(addr));
}
__device__ __forceinline__ void ldsm_x2(uint32_t r[2], uint32_t addr) {
  asm volatile("ldmatrix.sync.aligned.m8n8.x2.shared.b16 {%0,%1}, [%2];"
               : "=r"(r[0]), "=r"(r[1]) : "r"(addr));
}

// Core 128x128 GEMM body via mma.sync tf32 (fp32 accumulate).
// Double-buffered smem; direct LDG->STS of chunk c+1 after MMA of chunk c;
// one __syncthreads per chunk. Designed for 2 CTAs/SM (cross-CTA overlap).
//   C[m,n] = alpha * sum_k A[m*sAm+k*sAk] * B[n*sBn+k*sBk] (+biases) ; C[m + n*sCn]
// EEPI: epilogue writes fast_exp(alpha*acc). NORM: A *= nrm (same addressing).
template <bool AKC, bool BKC, bool NORM, bool EEPI>
__device__ __forceinline__ void gemm_body(
    const float* __restrict__ A, long sAm, long sAk,
    const float* __restrict__ Bp, long sBn, long sBk,
    float* __restrict__ Cp, long sCn,
    const float* __restrict__ nrm,
    const float* __restrict__ bias_m, const float* __restrict__ bias_n,
    float alpha, int K) {
  __shared__ uint32_t As[2][kBufW];
  __shared__ uint32_t Bs[2][kBufW];
  __shared__ float bmS[128], bnS[128];

  const int tid = threadIdx.x;
  const int lane = tid & 31, wid = tid >> 5;
  const int wm = (wid & 1) * 64, wn = (wid >> 1) * 32;
  const int row = tid >> 1, khalf = (tid & 1) * 16;

  if (!EEPI && tid < 128) {
    bmS[tid] = bias_m ? bias_m[tid] : 0.f;
    bnS[tid] = bias_n ? bias_n[tid] : 0.f;
  }

  const float* Arow = A + (long)row * sAm + (long)khalf * sAk;
  const float* Brow = Bp + (long)row * sBn + (long)khalf * sBk;
  const float* Nrow = NORM ? nrm + (long)row * sAm + (long)khalf * sAk : nullptr;
  uint32_t* const sA = &As[0][0] + row * kLds + khalf;
  uint32_t* const sB = &Bs[0][0] + row * kLds + khalf;

  // ldmatrix per-lane address offsets (bytes).
  const uint32_t a_off =
      (uint32_t)((((lane & 7) + ((lane >> 3) & 1) * 8) * kLds + (lane >> 4) * 4) * 4);
  const uint32_t b_off = (uint32_t)(((lane & 7) * kLds + ((lane >> 3) & 1) * 4) * 4);
  const uint32_t saA0 = smem_u32(As) + (uint32_t)(wm * kLds * 4) + a_off;
  const uint32_t saB0 = smem_u32(Bs) + (uint32_t)(wn * kLds * 4) + b_off;

  // Chunk 0.
  load_store16<AKC, NORM>(sA, Arow, sAk, Nrow);
  load_store16<BKC, false>(sB, Brow, sBk, nullptr);
  __syncthreads();

  float acc[4][4][4];
#pragma unroll
  for (int i = 0; i < 4; i++)
#pragma unroll
    for (int j = 0; j < 4; j++)
#pragma unroll
      for (int c = 0; c < 4; c++) acc[i][j][c] = 0.f;

  const int nch = K >> 5;
  for (int c = 0; c < nch; c++) {
    const uint32_t stg = (uint32_t)((c & 1) * kBufW * 4);
    const uint32_t aBase = saA0 + stg;
    const uint32_t bBase = saB0 + stg;

#pragma unroll
    for (int ks = 0; ks < 4; ks++) {
      uint32_t af[4][4], bf[4][2];
#pragma unroll
      for (int im = 0; im < 4; im++)
        ldsm_x4(af[im], aBase + (uint32_t)((im * 16 * kLds + ks * 8) * 4));
#pragma unroll
      for (int in = 0; in < 4; in++)
        ldsm_x2(bf[in], bBase + (uint32_t)((in * 8 * kLds + ks * 8) * 4));
#pragma unroll
      for (int im = 0; im < 4; im++)
#pragma unroll
        for (int in = 0; in < 4; in++) {
          asm volatile(
              "mma.sync.aligned.m16n8k8.row.col.f32.tf32.tf32.f32 "
              "{%0,%1,%2,%3}, {%4,%5,%6,%7}, {%8,%9}, {%0,%1,%2,%3};"
              : "+f"(acc[im][in][0]), "+f"(acc[im][in][1]), "+f"(acc[im][in][2]),
                "+f"(acc[im][in][3])
              : "r"(af[im][0]), "r"(af[im][1]), "r"(af[im][2]), "r"(af[im][3]),
                "r"(bf[in][0]), "r"(bf[in][1]));
        }
    }
    if (c + 1 < nch) {
      const int nb = (c + 1) & 1;
      const long ko = (long)(c + 1) * 32;
      load_store16<AKC, NORM>(sA + nb * kBufW, Arow + ko * sAk, sAk,
                              NORM ? Nrow + ko * sAk : nullptr);
      load_store16<BKC, false>(sB + nb * kBufW, Brow + ko * sBk, sBk, nullptr);
    }
    __syncthreads();
  }

  const int g = lane >> 2, t2 = (lane & 3) * 2;
#pragma unroll
  for (int im = 0; im < 4; im++) {
    int m0 = wm + im * 16 + g;
    int m1 = m0 + 8;
    float bm0 = EEPI ? 0.f : bmS[m0], bm1 = EEPI ? 0.f : bmS[m1];
#pragma unroll
    for (int in = 0; in < 4; in++) {
      int n0 = wn + in * 8 + t2;
      int n1 = n0 + 1;
      if (EEPI) {
        Cp[(long)n0 * sCn + m0] = fast_exp(alpha * acc[im][in][0]);
        Cp[(long)n1 * sCn + m0] = fast_exp(alpha * acc[im][in][1]);
        Cp[(long)n0 * sCn + m1] = fast_exp(alpha * acc[im][in][2]);
        Cp[(long)n1 * sCn + m1] = fast_exp(alpha * acc[im][in][3]);
      } else {
        float bn0 = bnS[n0], bn1 = bnS[n1];
        Cp[(long)n0 * sCn + m0] = alpha * acc[im][in][0] + bm0 + bn0;
        Cp[(long)n1 * sCn + m0] = alpha * acc[im][in][1] + bm0 + bn1;
        Cp[(long)n0 * sCn + m1] = alpha * acc[im][in][2] + bm1 + bn0;
        Cp[(long)n1 * sCn + m1] = alpha * acc[im][in][3] + bm1 + bn1;
      }
    }
  }
}

// Fused QKV: grid (1, 3, B*H); y selects weight/bias/output; x tile reused via L2.
__global__ __launch_bounds__(256, 2) void gemm_qkv(
    const float* __restrict__ x,
    const float* __restrict__ Wq, const float* __restrict__ Wk, const float* __restrict__ Wv,
    const float* __restrict__ bq, const float* __restrict__ bk, const float* __restrict__ bv,
    float* __restrict__ q, float* __restrict__ k, float* __restrict__ v) {
  const int z = blockIdx.z, y = blockIdx.y;
  const float* A = (y == 0) ? Wq : (y == 1) ? Wk : Wv;
  const float* bm = (y == 0) ? bq : (y == 1) ? bk : bv;
  float* C = ((y == 0) ? q : (y == 1) ? k : v) +
             (long)(z / kH) * ((long)kW * kH * kC) + (long)(z % kH) * kC;
  const float* B = x + (long)z * kC * kW;
  gemm_body<false, false, false, false>(A, 1, kC, B, 1, kW, C, (long)kH * kC,
                                        nullptr, bm, nullptr, 1.f, kC);
}

template <bool AKC, bool BKC, bool NORM, bool EEPI>
__global__ __launch_bounds__(256, 2) void gemm_gen(
    const float* __restrict__ A, int a_div, long a_so, long a_si, long sAm, long sAk,
    const float* __restrict__ Bp, int b_div, long b_so, long b_si, long sBn, long sBk,
    float* __restrict__ Cp, int c_div, long c_so, long c_si, long sCn,
    const float* __restrict__ nrm_base, int nrm_div,
    const float* __restrict__ bias_m, const float* __restrict__ bias_n,
    float alpha, int K) {
  const int z = blockIdx.z, bx = blockIdx.x, by = blockIdx.y;
  A += (long)(z / a_div) * a_so + (long)(z % a_div) * a_si + (long)bx * 128 * sAm;
  Bp += (long)(z / b_div) * b_so + (long)(z % b_div) * b_si + (long)by * 128 * sBn;
  Cp += (long)(z / c_div) * c_so + (long)(z % c_div) * c_si + (long)bx * 128 +
        (long)by * 128 * sCn;
  const float* nrm = nullptr;
  if (NORM) nrm = nrm_base + (long)(z / nrm_div) * kCC + (long)bx * 128 * sAm;
  gemm_body<AKC, BKC, NORM, EEPI>(A, sAm, sAk, Bp, sBn, sBk, Cp, sCn, nrm,
                                  bias_m ? bias_m + bx * 128 : nullptr,
                                  bias_n ? bias_n + by * 128 : nullptr, alpha, K);
}

// Per-(b,d,c) reciprocal of sum over w of exp(scores) stored in s (B,W,D,C).
__global__ __launch_bounds__(256) void softmax_sum(const float* __restrict__ s,
                                                   float* __restrict__ inv) {
  long t = (long)blockIdx.x * blockDim.x + threadIdx.x;  // < B*C*C
  int b = (int)(t / kCC);
  int r = (int)(t % kCC);
  const float* p = s + (long)b * kW * kCC + r;
  float l = 0.f;
#pragma unroll 8
  for (int w = 0; w < kW; w++) l += p[(long)w * kCC];
  inv[t] = 1.f / l;
}

// Transpose m5 (B,W,C,H) -> m6 (B,H,C,W).
__global__ __launch_bounds__(256) void trans_wh(const float* __restrict__ in,
                                                float* __restrict__ out) {
  __shared__ float tile[32][33];
  int bc = blockIdx.z;
  int b = bc / kC, c = bc % kC;
  long ibase = (long)b * kW * kC * kH + (long)c * kH;
  long obase = (long)b * kH * kC * kW + (long)c * kW;
  int w0 = blockIdx.x * 32, h0 = blockIdx.y * 32;
  int txl = threadIdx.x;
#pragma unroll
  for (int i = threadIdx.y; i < 32; i += 8)
    tile[i][txl] = in[ibase + (long)(w0 + i) * (kC * kH) + h0 + txl];
  __syncthreads();
#pragma unroll
  for (int i = threadIdx.y; i < 32; i += 8)
    out[obase + (long)(h0 + i) * (kC * kW) + w0 + txl] = tile[txl][i];
}

extern "C" void kernel_launch(void* const* d_in, const int* in_sizes, int n_in,
                              void* d_out, int out_size) {
  (void)in_sizes; (void)n_in; (void)out_size;
  const float* x  = (const float*)d_in[0];
  const float* Wq = (const float*)d_in[1];
  const float* bq = (const float*)d_in[2];
  const float* Wk = (const float*)d_in[3];
  const float* bk = (const float*)d_in[4];
  const float* Wv = (const float*)d_in[5];
  const float* bv = (const float*)d_in[6];
  const float* Wn = (const float*)d_in[7];
  const float* bn = (const float*)d_in[8];
  const float* Wo = (const float*)d_in[9];
  const float* bo = (const float*)d_in[10];
  float* out = (float*)d_out;

  float *q, *k, *v, *s, *wn, *inv;
  cudaGetSymbolAddress((void**)&q, g_q);
  cudaGetSymbolAddress((void**)&k, g_k);
  cudaGetSymbolAddress((void**)&v, g_v);
  cudaGetSymbolAddress((void**)&s, g_s);
  cudaGetSymbolAddress((void**)&wn, g_wn);
  cudaGetSymbolAddress((void**)&inv, g_inv);

  const long HC = (long)kH * kC;
  const long CW = (long)kC * kW;
  const long CC = kCC;
  const long CH = (long)kC * kH;

  // Pass 1: fused Q/K/V projections. z=(b*H+h), y selects head. m=d, n=w, k=c.
  gemm_qkv<<<dim3(1, 3, kB * kH), 256>>>(x, Wq, Wk, Wv, bq, bk, bv, q, k, v);

  // Pass 2: s[b,w][c,d] = exp(sum_h q*k / sqrt(W)). z=(b*W+w). m=c, n=d, k=h.
  gemm_gen<false, false, false, true><<<dim3(1, 1, kB * kW), 256>>>(
      q, 1, HC, 0, 1, kC,
      k, 1, HC, 0, 1, kC,
      s, 1, CC, 0, kC,
      nullptr, 1, nullptr, nullptr, 0.08838834764831845f, kH);

  // Pass 3: softmax denominators.
  softmax_sum<<<(int)((kB * CC) / 256), 256>>>(s, inv);

  // Pass 4: wn[b,w][c,e] = sum_d (e*inv)[d,c]*Wn[d,e] + bn[e]. m=c, n=e, k=d.
  gemm_gen<false, false, true, false><<<dim3(1, 1, kB * kW), 256>>>(
      s, 1, CC, 0, 1, kC,
      Wn, 1, 0, 0, 1, kC,
      wn, 1, CC, 0, kC,
      inv, kW, nullptr, bn, 1.f, kC);

  // Pass 5: m[b,w][h,c] = sum_e v[h,e]*wn[e,c]. m=h (grid.x=2), n=c, k=e.
  gemm_gen<true, false, false, false><<<dim3(2, 1, kB * kW), 256>>>(
      v, 1, HC, 0, kC, 1,
      wn, 1, CC, 0, 1, kC,
      q, 1, CH, 0, kH,
      nullptr, 1, nullptr, nullptr, 1.f, kC);

  // Pass 5.5: transpose m5 (B,W,C,H) -> m6 (B,H,C,W).
  trans_wh<<<dim3(kW / 32, kH / 32, kB * kC), dim3(32, 8)>>>(q, k);

  // Pass 6: out[b,h][w,o] = sum_c m6[c,w]*Wo[c,o] + bo[o]. m=w, n=o, k=c.
  gemm_gen<false, false, false, false><<<dim3(1, 1, kB * kH), 256>>>(
      k, 1, CW, 0, 1, kW,
      Wo, 1, 0, 0, 1, kC,
      out, 1, CW, 0, kW,
      nullptr, 1, nullptr, bo, 1.f, kC);
}

// round 10
// speedup vs baseline: 1.0236x; 1.0236x over previous
#include <cuda_runtime.h>
#include <cstdint>

namespace {
constexpr int kB = 16, kH = 256, kC = 128, kW = 128;
constexpr long kCC = (long)kC * kC;
}

// Scratch (device globals: allocation-free contract).
__device__ float g_q[(size_t)kB * kW * kH * kC];   // q (B,W,H,C); reused as m5 (B,W,C,H)
__device__ float g_k[(size_t)kB * kW * kH * kC];   // k (B,W,H,C); reused as m6 (B,H,C,W)
__device__ float g_v[(size_t)kB * kW * kH * kC];   // v (B,W,H,C)
__device__ float g_s[(size_t)kB * kW * kC * kC];   // exp(scores) (B,W,D,C)
__device__ float g_inv[(size_t)kB * kC * kC];      // 1/sum_w exp (B,D,C)

__device__ __forceinline__ uint32_t smem_u32(const void* p) {
  uint32_t a;
  asm("{ .reg .u64 t; cvta.to.shared.u64 t, %1; cvt.u32.u64 %0, t; }" : "=r"(a) : "l"(p));
  return a;
}
__device__ __forceinline__ uint32_t f2tf32(float f) {
  uint32_t r;
  asm("cvt.rna.tf32.f32 %0, %1;" : "=r"(r) : "f"(f));
  return r;
}

// exp on the FMA pipe (no MUFU): exp(x) = 2^r * e^f, deg-5 Taylor on |f|<=ln2/2.
__device__ __forceinline__ float fast_exp(float x) {
  x = fminf(fmaxf(x, -30.f), 30.f);
  float r = rintf(x * 1.44269504f);
  float f = fmaf(r, -0.6931471805599453f, x);
  float p = 1.f + f * (1.f + f * (0.5f + f * (0.16666667f +
                f * (0.041666667f + f * 0.0083333333f))));
  return p * __int_as_float(((int)r + 127) << 23);
}

// SMEM row stride (words). 36 => ldmatrix phases span all 32 banks (4r+c).
constexpr int kLds = 36;
constexpr int kBufW = 128 * kLds;   // words per stage (4608)
constexpr int kWnS = 132;           // wn smem row stride (132 % 32 == 4)
constexpr int kWnWords = 128 * kWnS;  // 16896

// Load 16 k-words of one row into registers. KC=true: k unit stride (float4).
template <bool KC>
__device__ __forceinline__ void ldg16(float4 r[4], const float* __restrict__ p, long sK) {
  if (KC) {
#pragma unroll
    for (int i = 0; i < 4; i++) r[i] = reinterpret_cast<const float4*>(p)[i];
  } else {
#pragma unroll
    for (int i = 0; i < 4; i++) {
      r[i].x = p[(long)(i * 4 + 0) * sK];
      r[i].y = p[(long)(i * 4 + 1) * sK];
      r[i].z = p[(long)(i * 4 + 2) * sK];
      r[i].w = p[(long)(i * 4 + 3) * sK];
    }
  }
}

// Convert to tf32 (optionally *nrm first) and store 16 contiguous words to smem.
template <bool NORM>
__device__ __forceinline__ void sts16(uint32_t* __restrict__ dst, const float4 a[4],
                                      const float4 n[4]) {
#pragma unroll
  for (int i = 0; i < 4; i++) {
    float4 v = a[i];
    if (NORM) {
      v.x *= n[i].x; v.y *= n[i].y; v.z *= n[i].z; v.w *= n[i].w;
    }
    uint32_t t0 = f2tf32(v.x), t1 = f2tf32(v.y), t2 = f2tf32(v.z), t3 = f2tf32(v.w);
    asm volatile("st.shared.v4.b32 [%0], {%1,%2,%3,%4};"
                 :: "l"(dst + i * 4), "r"(t0), "r"(t1), "r"(t2), "r"(t3));
  }
}

// Direct gmem -> smem (short-lived register temps only).
template <bool KC, bool NORM>
__device__ __forceinline__ void load_store16(uint32_t* __restrict__ dst,
                                             const float* __restrict__ src, long sK,
                                             const float* __restrict__ nsrc) {
  float4 a[4], n[4];
  ldg16<KC>(a, src, sK);
  if (NORM) ldg16<KC>(n, nsrc, sK);
  sts16<NORM>(dst, a, n);
}

__device__ __forceinline__ void ldsm_x4(uint32_t r[4], uint32_t addr) {
  asm volatile("ldmatrix.sync.aligned.m8n8.x4.shared.b16 {%0,%1,%2,%3}, [%4];"
               : "=r"(r[0]), "=r"(r[1]), "=r"(r[2]), "=r"(r[3]) : "r"(addr));
}

// Per-lane byte offsets for ldmatrix.x4.
// A (4 matrices = rows m..m+15 x word-halves): lanes 8-15 -> rows+8, 16-31 -> words+4.
__device__ __forceinline__ uint32_t a4_off(int lane, int stride) {
  return (uint32_t)(((((lane & 7) + ((lane >> 3) & 1) * 8) * stride) + (lane >> 4) * 4) * 4);
}
// B (4 matrices = two 8-row n-tiles x word-halves): 8-15 -> words+4, 16-31 -> rows+8.
__device__ __forceinline__ uint32_t b4_off(int lane, int stride) {
  return (uint32_t)(((((lane & 7) + ((lane >> 4) & 1) * 8) * stride) + ((lane >> 3) & 1) * 4) * 4);
}

__device__ __forceinline__ void mma_tf32(float acc[4], const uint32_t a[4],
                                         const uint32_t b[2]) {
  asm volatile(
      "mma.sync.aligned.m16n8k8.row.col.f32.tf32.tf32.f32 "
      "{%0,%1,%2,%3}, {%4,%5,%6,%7}, {%8,%9}, {%0,%1,%2,%3};"
      : "+f"(acc[0]), "+f"(acc[1]), "+f"(acc[2]), "+f"(acc[3])
      : "r"(a[0]), "r"(a[1]), "r"(a[2]), "r"(a[3]), "r"(b[0]), "r"(b[1]));
}

// One ks-step of the 64x32 warp tile: A x4 loads, B x4-pair loads, 16 MMAs.
__device__ __forceinline__ void warp_mma_step(float acc[4][4][4], uint32_t aBase,
                                              uint32_t bBase, int ks, int strideB) {
  uint32_t af[4][4], bf[4][2];
#pragma unroll
  for (int im = 0; im < 4; im++)
    ldsm_x4(af[im], aBase + (uint32_t)((im * 16 * kLds + ks * 8) * 4));
  {
    uint32_t bt[4];
    ldsm_x4(bt, bBase + (uint32_t)((ks * 8) * 4));
    bf[0][0] = bt[0]; bf[0][1] = bt[1]; bf[1][0] = bt[2]; bf[1][1] = bt[3];
    ldsm_x4(bt, bBase + (uint32_t)((16 * strideB + ks * 8) * 4));
    bf[2][0] = bt[0]; bf[2][1] = bt[1]; bf[3][0] = bt[2]; bf[3][1] = bt[3];
  }
#pragma unroll
  for (int im = 0; im < 4; im++)
#pragma unroll
    for (int in = 0; in < 4; in++) mma_tf32(acc[im][in], af[im], bf[in]);
}

// Core 128x128 GEMM body via mma.sync tf32 (fp32 accumulate).
// Double-buffered smem; direct LDG->STS of chunk c+1 after MMA of chunk c;
// one __syncthreads per chunk. 2 CTAs/SM for cross-CTA overlap.
template <bool AKC, bool BKC, bool NORM, bool EEPI>
__device__ __forceinline__ void gemm_body(
    const float* __restrict__ A, long sAm, long sAk,
    const float* __restrict__ Bp, long sBn, long sBk,
    float* __restrict__ Cp, long sCn,
    const float* __restrict__ nrm,
    const float* __restrict__ bias_m, const float* __restrict__ bias_n,
    float alpha, int K) {
  __shared__ uint32_t As[2][kBufW];
  __shared__ uint32_t Bs[2][kBufW];
  __shared__ float bmS[128], bnS[128];

  const int tid = threadIdx.x;
  const int lane = tid & 31, wid = tid >> 5;
  const int wm = (wid & 1) * 64, wn = (wid >> 1) * 32;
  const int row = tid >> 1, khalf = (tid & 1) * 16;

  if (!EEPI && tid < 128) {
    bmS[tid] = bias_m ? bias_m[tid] : 0.f;
    bnS[tid] = bias_n ? bias_n[tid] : 0.f;
  }

  const float* Arow = A + (long)row * sAm + (long)khalf * sAk;
  const float* Brow = Bp + (long)row * sBn + (long)khalf * sBk;
  const float* Nrow = NORM ? nrm + (long)row * sAm + (long)khalf * sAk : nullptr;
  uint32_t* const sA = &As[0][0] + row * kLds + khalf;
  uint32_t* const sB = &Bs[0][0] + row * kLds + khalf;

  const uint32_t saA0 = smem_u32(As) + (uint32_t)(wm * kLds * 4) + a4_off(lane, kLds);
  const uint32_t saB0 = smem_u32(Bs) + (uint32_t)(wn * kLds * 4) + b4_off(lane, kLds);

  // Chunk 0.
  load_store16<AKC, NORM>(sA, Arow, sAk, Nrow);
  load_store16<BKC, false>(sB, Brow, sBk, nullptr);
  __syncthreads();

  float acc[4][4][4];
#pragma unroll
  for (int i = 0; i < 4; i++)
#pragma unroll
    for (int j = 0; j < 4; j++)
#pragma unroll
      for (int c = 0; c < 4; c++) acc[i][j][c] = 0.f;

  const int nch = K >> 5;
  for (int c = 0; c < nch; c++) {
    const uint32_t stg = (uint32_t)((c & 1) * kBufW * 4);
#pragma unroll
    for (int ks = 0; ks < 4; ks++)
      warp_mma_step(acc, saA0 + stg, saB0 + stg, ks, kLds);
    if (c + 1 < nch) {
      const int nb = (c + 1) & 1;
      const long ko = (long)(c + 1) * 32;
      load_store16<AKC, NORM>(sA + nb * kBufW, Arow + ko * sAk, sAk,
                              NORM ? Nrow + ko * sAk : nullptr);
      load_store16<BKC, false>(sB + nb * kBufW, Brow + ko * sBk, sBk, nullptr);
    }
    __syncthreads();
  }

  const int g = lane >> 2, t2 = (lane & 3) * 2;
#pragma unroll
  for (int im = 0; im < 4; im++) {
    int m0 = wm + im * 16 + g;
    int m1 = m0 + 8;
    float bm0 = EEPI ? 0.f : bmS[m0], bm1 = EEPI ? 0.f : bmS[m1];
#pragma unroll
    for (int in = 0; in < 4; in++) {
      int n0 = wn + in * 8 + t2;
      int n1 = n0 + 1;
      if (EEPI) {
        Cp[(long)n0 * sCn + m0] = fast_exp(alpha * acc[im][in][0]);
        Cp[(long)n1 * sCn + m0] = fast_exp(alpha * acc[im][in][1]);
        Cp[(long)n0 * sCn + m1] = fast_exp(alpha * acc[im][in][2]);
        Cp[(long)n1 * sCn + m1] = fast_exp(alpha * acc[im][in][3]);
      } else {
        float bn0 = bnS[n0], bn1 = bnS[n1];
        Cp[(long)n0 * sCn + m0] = alpha * acc[im][in][0] + bm0 + bn0;
        Cp[(long)n1 * sCn + m0] = alpha * acc[im][in][1] + bm0 + bn1;
        Cp[(long)n0 * sCn + m1] = alpha * acc[im][in][2] + bm1 + bn0;
        Cp[(long)n1 * sCn + m1] = alpha * acc[im][in][3] + bm1 + bn1;
      }
    }
  }
}

// Fused QKV: grid (1, 3, B*H); y selects weight/bias/output; x tile reused via L2.
__global__ __launch_bounds__(256, 2) void gemm_qkv(
    const float* __restrict__ x,
    const float* __restrict__ Wq, const float* __restrict__ Wk, const float* __restrict__ Wv,
    const float* __restrict__ bq, const float* __restrict__ bk, const float* __restrict__ bv,
    float* __restrict__ q, float* __restrict__ k, float* __restrict__ v) {
  const int z = blockIdx.z, y = blockIdx.y;
  const float* A = (y == 0) ? Wq : (y == 1) ? Wk : Wv;
  const float* bm = (y == 0) ? bq : (y == 1) ? bk : bv;
  float* C = ((y == 0) ? q : (y == 1) ? k : v) +
             (long)(z / kH) * ((long)kW * kH * kC) + (long)(z % kH) * kC;
  const float* B = x + (long)z * kC * kW;
  gemm_body<false, false, false, false>(A, 1, kC, B, 1, kW, C, (long)kH * kC,
                                        nullptr, bm, nullptr, 1.f, kC);
}

template <bool AKC, bool BKC, bool NORM, bool EEPI>
__global__ __launch_bounds__(256, 2) void gemm_gen(
    const float* __restrict__ A, int a_div, long a_so, long a_si, long sAm, long sAk,
    const float* __restrict__ Bp, int b_div, long b_so, long b_si, long sBn, long sBk,
    float* __restrict__ Cp, int c_div, long c_so, long c_si, long sCn,
    const float* __restrict__ nrm_base, int nrm_div,
    const float* __restrict__ bias_m, const float* __restrict__ bias_n,
    float alpha, int K) {
  const int z = blockIdx.z, bx = blockIdx.x, by = blockIdx.y;
  A += (long)(z / a_div) * a_so + (long)(z % a_div) * a_si + (long)bx * 128 * sAm;
  Bp += (long)(z / b_div) * b_so + (long)(z % b_div) * b_si + (long)by * 128 * sBn;
  Cp += (long)(z / c_div) * c_so + (long)(z % c_div) * c_si + (long)bx * 128 +
        (long)by * 128 * sCn;
  const float* nrm = nullptr;
  if (NORM) nrm = nrm_base + (long)(z / nrm_div) * kCC + (long)bx * 128 * sAm;
  gemm_body<AKC, BKC, NORM, EEPI>(A, sAm, sAk, Bp, sBn, sBk, Cp, sCn, nrm,
                                  bias_m ? bias_m + bx * 128 : nullptr,
                                  bias_n ? bias_n + by * 128 : nullptr, alpha, K);
}

// Fused pass4+pass5 per z=(b,w):
//   GEMM1: wn[c,e] = sum_d (s*inv)[d,c] * Wn[d,e] + bn[e]  -> smem (tf32, [c][e])
//   GEMM2 (hh=0,1): m5[c, hh*128+h] = sum_e v[hh*128+h, e] * wn[e, c]
// Dynamic smem: [0, 2*kBufW) A stages; [2*kBufW, +2*kBufW) B stages (GEMM1),
// aliased by wn tile [2*kBufW, 2*kBufW + kWnWords) after GEMM1 completes.
__global__ __launch_bounds__(256, 2) void gemm_p45(
    const float* __restrict__ s, const float* __restrict__ Wn,
    const float* __restrict__ inv, const float* __restrict__ v,
    const float* __restrict__ bn, float* __restrict__ m5) {
  extern __shared__ uint32_t dynS[];
  uint32_t* const SA = dynS;
  uint32_t* const SB = dynS + 2 * kBufW;
  uint32_t* const WNS = dynS + 2 * kBufW;  // alias of SB region (+ extension)
  __shared__ float bnS[128];

  const int tid = threadIdx.x;
  const int lane = tid & 31, wid = tid >> 5;
  const int wm = (wid & 1) * 64, wn = (wid >> 1) * 32;
  const int row = tid >> 1, khalf = (tid & 1) * 16;
  const int z = blockIdx.z;
  const int b = z >> 7;  // z = b*kW + w

  if (tid < 128) bnS[tid] = bn[tid];

  // GEMM1 operands: A[m=c + k=d*kC] = s + z*CC ; nrm same idx; B[n=e + k=d*kC] = Wn.
  const float* Arow1 = s + (long)z * kCC + row + (long)khalf * kC;
  const float* Nrow1 = inv + (long)b * kCC + row + (long)khalf * kC;
  const float* Brow1 = Wn + row + (long)khalf * kC;
  uint32_t* const sAp = SA + row * kLds + khalf;
  uint32_t* const sBp = SB + row * kLds + khalf;

  const uint32_t saA0 = smem_u32(SA) + (uint32_t)(wm * kLds * 4) + a4_off(lane, kLds);
  const uint32_t saB0 = smem_u32(SB) + (uint32_t)(wn * kLds * 4) + b4_off(lane, kLds);

  load_store16<false, true>(sAp, Arow1, kC, Nrow1);
  load_store16<false, false>(sBp, Brow1, kC, nullptr);
  __syncthreads();

  float acc[4][4][4];
#pragma unroll
  for (int i = 0; i < 4; i++)
#pragma unroll
    for (int j = 0; j < 4; j++)
#pragma unroll
      for (int c = 0; c < 4; c++) acc[i][j][c] = 0.f;

  for (int c = 0; c < 4; c++) {
    const uint32_t stg = (uint32_t)((c & 1) * kBufW * 4);
#pragma unroll
    for (int ks = 0; ks < 4; ks++)
      warp_mma_step(acc, saA0 + stg, saB0 + stg, ks, kLds);
    if (c + 1 < 4) {
      const int nb = (c + 1) & 1;
      const long ko = (long)(c + 1) * 32;
      load_store16<false, true>(sAp + nb * kBufW, Arow1 + ko * kC, kC, Nrow1 + ko * kC);
      load_store16<false, false>(sBp + nb * kBufW, Brow1 + ko * kC, kC, nullptr);
    }
    __syncthreads();
  }

  // Epilogue1: wn tile -> WNS[c*kWnS + e], tf32-rounded, +bn[e].
  const int g = lane >> 2, t2 = (lane & 3) * 2;
#pragma unroll
  for (int im = 0; im < 4; im++) {
    int m0 = wm + im * 16 + g;
    int m1 = m0 + 8;
#pragma unroll
    for (int in = 0; in < 4; in++) {
      int n0 = wn + in * 8 + t2;
      int n1 = n0 + 1;
      WNS[m0 * kWnS + n0] = f2tf32(acc[im][in][0] + bnS[n0]);
      WNS[m0 * kWnS + n1] = f2tf32(acc[im][in][1] + bnS[n1]);
      WNS[m1 * kWnS + n0] = f2tf32(acc[im][in][2] + bnS[n0]);
      WNS[m1 * kWnS + n1] = f2tf32(acc[im][in][3] + bnS[n1]);
    }
  }
  __syncthreads();

  // GEMM2: A[m=h, k=e] = v[z, h, e] (k unit stride); B from WNS ([n=c][k=e]).
  const float* vz = v + (long)z * kH * kC;
  float* const mz = m5 + (long)z * kC * kH;
  const uint32_t saB2 = smem_u32(WNS) + (uint32_t)(wn * kWnS * 4) + b4_off(lane, kWnS);

  for (int hh = 0; hh < 2; hh++) {
    const float* Arow2 = vz + (long)(hh * 128 + row) * kC + khalf;
    load_store16<true, false>(sAp, Arow2, 1, nullptr);
    __syncthreads();

#pragma unroll
    for (int i = 0; i < 4; i++)
#pragma unroll
      for (int j = 0; j < 4; j++)
#pragma unroll
        for (int c = 0; c < 4; c++) acc[i][j][c] = 0.f;

    for (int c = 0; c < 4; c++) {
      const uint32_t aBase = saA0 + (uint32_t)((c & 1) * kBufW * 4);
      const uint32_t bBase = saB2 + (uint32_t)((c * 32) * 4);
#pragma unroll
      for (int ks = 0; ks < 4; ks++)
        warp_mma_step(acc, aBase, bBase, ks, kWnS);
      if (c + 1 < 4) {
        const int nb = (c + 1) & 1;
        load_store16<true, false>(sAp + nb * kBufW, Arow2 + (c + 1) * 32, 1, nullptr);
      }
      __syncthreads();
    }

#pragma unroll
    for (int im = 0; im < 4; im++) {
      int m0 = hh * 128 + wm + im * 16 + g;
      int m1 = m0 + 8;
#pragma unroll
      for (int in = 0; in < 4; in++) {
        int n0 = wn + in * 8 + t2;
        int n1 = n0 + 1;
        mz[(long)n0 * kH + m0] = acc[im][in][0];
        mz[(long)n1 * kH + m0] = acc[im][in][1];
        mz[(long)n0 * kH + m1] = acc[im][in][2];
        mz[(long)n1 * kH + m1] = acc[im][in][3];
      }
    }
  }
}

// Per-(b,d,c) reciprocal of sum over w of exp(scores) stored in s (B,W,D,C).
__global__ __launch_bounds__(256) void softmax_sum(const float* __restrict__ s,
                                                   float* __restrict__ inv) {
  long t = (long)blockIdx.x * blockDim.x + threadIdx.x;  // < B*C*C
  int b = (int)(t / kCC);
  int r = (int)(t % kCC);
  const float* p = s + (long)b * kW * kCC + r;
  float l = 0.f;
#pragma unroll 8
  for (int w = 0; w < kW; w++) l += p[(long)w * kCC];
  inv[t] = 1.f / l;
}

// Transpose m5 (B,W,C,H) -> m6 (B,H,C,W).
__global__ __launch_bounds__(256) void trans_wh(const float* __restrict__ in,
                                                float* __restrict__ out) {
  __shared__ float tile[32][33];
  int bc = blockIdx.z;
  int b = bc / kC, c = bc % kC;
  long ibase = (long)b * kW * kC * kH + (long)c * kH;
  long obase = (long)b * kH * kC * kW + (long)c * kW;
  int w0 = blockIdx.x * 32, h0 = blockIdx.y * 32;
  int txl = threadIdx.x;
#pragma unroll
  for (int i = threadIdx.y; i < 32; i += 8)
    tile[i][txl] = in[ibase + (long)(w0 + i) * (kC * kH) + h0 + txl];
  __syncthreads();
#pragma unroll
  for (int i = threadIdx.y; i < 32; i += 8)
    out[obase + (long)(h0 + i) * (kC * kW) + w0 + txl] = tile[txl][i];
}

extern "C" void kernel_launch(void* const* d_in, const int* in_sizes, int n_in,
                              void* d_out, int out_size) {
  (void)in_sizes; (void)n_in; (void)out_size;
  const float* x  = (const float*)d_in[0];
  const float* Wq = (const float*)d_in[1];
  const float* bq = (const float*)d_in[2];
  const float* Wk = (const float*)d_in[3];
  const float* bk = (const float*)d_in[4];
  const float* Wv = (const float*)d_in[5];
  const float* bv = (const float*)d_in[6];
  const float* Wn = (const float*)d_in[7];
  const float* bn = (const float*)d_in[8];
  const float* Wo = (const float*)d_in[9];
  const float* bo = (const float*)d_in[10];
  float* out = (float*)d_out;

  float *q, *k, *v, *s, *inv;
  cudaGetSymbolAddress((void**)&q, g_q);
  cudaGetSymbolAddress((void**)&k, g_k);
  cudaGetSymbolAddress((void**)&v, g_v);
  cudaGetSymbolAddress((void**)&s, g_s);
  cudaGetSymbolAddress((void**)&inv, g_inv);

  const long HC = (long)kH * kC;
  const long CW = (long)kC * kW;
  const long CC = kCC;

  // Pass 1: fused Q/K/V projections. z=(b*H+h), y selects head. m=d, n=w, k=c.
  gemm_qkv<<<dim3(1, 3, kB * kH), 256>>>(x, Wq, Wk, Wv, bq, bk, bv, q, k, v);

  // Pass 2: s[b,w][c,d] = exp(sum_h q*k / sqrt(W)). z=(b*W+w). m=c, n=d, k=h.
  gemm_gen<false, false, false, true><<<dim3(1, 1, kB * kW), 256>>>(
      q, 1, HC, 0, 1, kC,
      k, 1, HC, 0, 1, kC,
      s, 1, CC, 0, kC,
      nullptr, 1, nullptr, nullptr, 0.08838834764831845f, kH);

  // Pass 3: softmax denominators.
  softmax_sum<<<(int)((kB * CC) / 256), 256>>>(s, inv);

  // Pass 4+5 fused: wn in smem, m5 (B,W,C,H) into g_q.
  const int dynBytes = (2 * kBufW + kWnWords) * 4;
  cudaFuncSetAttribute(gemm_p45, cudaFuncAttributeMaxDynamicSharedMemorySize, dynBytes);
  gemm_p45<<<dim3(1, 1, kB * kW), 256, dynBytes>>>(s, Wn, inv, v, bn, q);

  // Pass 5.5: transpose m5 (B,W,C,H) -> m6 (B,H,C,W).
  trans_wh<<<dim3(kW / 32, kH / 32, kB * kC), dim3(32, 8)>>>(q, k);

  // Pass 6: out[b,h][w,o] = sum_c m6[c,w]*Wo[c,o] + bo[o]. m=w, n=o, k=c.
  gemm_gen<false, false, false, false><<<dim3(1, 1, kB * kH), 256>>>(
      k, 1, CW, 0, 1, kW,
      Wo, 1, 0, 0, 1, kC,
      out, 1, CW, 0, kW,
      nullptr, 1, nullptr, bo, 1.f, kC);
}